// round 9
// baseline (speedup 1.0000x reference)
#include <cuda_runtime.h>
#include <math.h>

#define NB 32
#define NC 256
#define NH 64
#define NW 64
#define HW (NH*NW)          // 4096
#define HW4 (HW/4)          // 1024 float4 groups per (b,c) plane
#define KS 7
#define PAD 3
#define TW 72               // padded conv tile width

#define CHUNK 16            // images per chunk (64 MiB, fits 126MB L2)
#define GRID 296            // 148 SMs x 2 CTAs, all co-resident
#define NT 512

// partial stats: [half][b][hw]  (half 0 = ch 0..127, half 1 = ch 128..255)
__device__ float g_pmax[2 * NB * HW];
__device__ float g_psum[2 * NB * HW];
__device__ float g_scale[NB * HW];

// global barrier state (zero-init; replay-safe sense-reversal)
__device__ unsigned g_count[8];
__device__ volatile unsigned g_sense[8];

__device__ __forceinline__ void gbar(int i)
{
    __syncthreads();
    if (threadIdx.x == 0) {
        unsigned s = g_sense[i];
        __threadfence();                       // release prior writes
        unsigned v = atomicAdd(&g_count[i], 1u);
        if (v == GRID - 1) {
            g_count[i] = 0;
            __threadfence();
            g_sense[i] = s ^ 1u;
        } else {
            while (g_sense[i] == s) { __nanosleep(64); }
        }
        __threadfence();                       // acquire
    }
    __syncthreads();
}

// ---------------------------------------------------------------------------
// Persistent kernel. Shared buffer reused across phases:
//   reduce: float4 s_max[16][32] + s_sum[16][32]  (16 KB)
//   conv:   4 tiles x 2 planes x 14 x TW floats   (32.25 KB)
// ---------------------------------------------------------------------------
__global__ void __launch_bounds__(NT, 2) persistent_kernel(const float* __restrict__ x,
                                                           const float* __restrict__ wgt,
                                                           float* __restrict__ out)
{
    __shared__ float4 sbuf[2048];        // 32 KB
    __shared__ float  sw[2 * KS * KS];

    const int tid = threadIdx.x;
    const int bid = blockIdx.x;
    if (tid < 2 * KS * KS) sw[tid] = wgt[tid];
    // sw consumed only after gbar(0) -> ordering covered

    // ------------------ phase lambdas (plain code, called per chunk) -------
    // ======== REDUCE: 1024 jobs; job = 32 f4-groups x (half of channels) ===
    #define PHASE_REDUCE(B0)                                                  \
    {                                                                         \
        float4* s_max = sbuf;          /* [16][32] */                         \
        float4* s_sum = sbuf + 512;    /* [16][32] */                         \
        int pix = tid & 31;                                                   \
        int cs  = tid >> 5;                                                   \
        for (int j = bid; j < 1024; j += GRID) {                              \
            int pairid = j >> 1;                                              \
            int half   = j & 1;                                               \
            int gp = pairid * 32 + pix;                                       \
            int b  = (B0) + (gp >> 10);                                       \
            int g  = gp & 1023;                                               \
            const float4* xb = reinterpret_cast<const float4*>(x)             \
                + ((size_t)b * NC + half * 128 + cs * 8) * HW4 + g;           \
            float4 mx = make_float4(-INFINITY,-INFINITY,-INFINITY,-INFINITY); \
            float4 sm = make_float4(0.f,0.f,0.f,0.f);                         \
            _Pragma("unroll")                                                 \
            for (int c = 0; c < 8; c++) {                                     \
                float4 v = __ldg(xb + c * HW4);                               \
                mx.x = fmaxf(mx.x, v.x);  sm.x += v.x;                        \
                mx.y = fmaxf(mx.y, v.y);  sm.y += v.y;                        \
                mx.z = fmaxf(mx.z, v.z);  sm.z += v.z;                        \
                mx.w = fmaxf(mx.w, v.w);  sm.w += v.w;                        \
            }                                                                 \
            s_max[cs * 32 + pix] = mx;                                        \
            s_sum[cs * 32 + pix] = sm;                                        \
            __syncthreads();                                                  \
            if (cs == 0) {                                                    \
                _Pragma("unroll")                                             \
                for (int k = 1; k < 16; k++) {                                \
                    float4 m = s_max[k * 32 + pix];                           \
                    float4 s = s_sum[k * 32 + pix];                           \
                    mx.x = fmaxf(mx.x, m.x);  sm.x += s.x;                    \
                    mx.y = fmaxf(mx.y, m.y);  sm.y += s.y;                    \
                    mx.z = fmaxf(mx.z, m.z);  sm.z += s.z;                    \
                    mx.w = fmaxf(mx.w, m.w);  sm.w += s.w;                    \
                }                                                             \
                size_t o = ((size_t)half * NB + b) * HW4 + g;                 \
                reinterpret_cast<float4*>(g_pmax)[o] = mx;                    \
                reinterpret_cast<float4*>(g_psum)[o] = sm;                    \
            }                                                                 \
            __syncthreads();                                                  \
        }                                                                     \
    }

    // ======== CONV: 128 strip jobs; 4 per CTA (one per 128-thread group) ===
    #define PHASE_CONV(B0)                                                    \
    {                                                                         \
        int group = tid >> 7;            /* 0..3 */                           \
        int wtid  = tid & 127;                                                \
        float* st = reinterpret_cast<float*>(sbuf) + group * (2 * 14 * TW);   \
        for (int base = bid * 4; base < 128; base += GRID * 4) {              \
            int j = base + group;                                             \
            int b = (B0) + (j >> 3);                                          \
            int h0 = (j & 7) * 8;                                             \
            const float* pmax0 = g_pmax + (size_t)b * HW;                     \
            const float* pmax1 = g_pmax + (size_t)(NB + b) * HW;              \
            const float* psum0 = g_psum + (size_t)b * HW;                     \
            const float* psum1 = g_psum + (size_t)(NB + b) * HW;              \
            for (int i = wtid; i < 2 * 14 * TW; i += 128) {                   \
                int plane = i / (14 * TW);                                    \
                int rem   = i % (14 * TW);                                    \
                int r = rem / TW;                                             \
                int c = rem % TW;                                             \
                int gr = h0 - PAD + r;                                        \
                int gc = c - PAD;                                             \
                float v = 0.f;                                                \
                if (gr >= 0 && gr < NH && gc >= 0 && gc < NW) {               \
                    int off = gr * NW + gc;                                   \
                    v = (plane == 0)                                          \
                      ? fmaxf(__ldg(pmax0 + off), __ldg(pmax1 + off))         \
                      : (__ldg(psum0 + off) + __ldg(psum1 + off))             \
                        * (1.0f / (float)NC);                                 \
                }                                                             \
                st[i] = v;                                                    \
            }                                                                 \
            __syncthreads();                                                  \
            int h_l = wtid >> 4;                                              \
            int w0c = (wtid & 15) << 2;                                       \
            float a0 = 0.f, a1 = 0.f, a2 = 0.f, a3 = 0.f;                     \
            _Pragma("unroll")                                                 \
            for (int kh = 0; kh < KS; kh++) {                                 \
                _Pragma("unroll")                                             \
                for (int kw = 0; kw < KS; kw++) {                             \
                    float wm = sw[kh * KS + kw];                              \
                    float wa = sw[KS * KS + kh * KS + kw];                    \
                    int r = h_l + kh;                                         \
                    int c = w0c + kw;                                         \
                    a0 += st[r * TW + c    ] * wm + st[14*TW + r*TW + c    ] * wa; \
                    a1 += st[r * TW + c + 1] * wm + st[14*TW + r*TW + c + 1] * wa; \
                    a2 += st[r * TW + c + 2] * wm + st[14*TW + r*TW + c + 2] * wa; \
                    a3 += st[r * TW + c + 3] * wm + st[14*TW + r*TW + c + 3] * wa; \
                }                                                             \
            }                                                                 \
            float4 s;                                                         \
            s.x = 1.0f / (1.0f + __expf(-a0));                                \
            s.y = 1.0f / (1.0f + __expf(-a1));                                \
            s.z = 1.0f / (1.0f + __expf(-a2));                                \
            s.w = 1.0f / (1.0f + __expf(-a3));                                \
            reinterpret_cast<float4*>(g_scale)                                \
                [(size_t)b * HW4 + (h0 + h_l) * 16 + (w0c >> 2)] = s;         \
            __syncthreads();                                                  \
        }                                                                     \
    }

    // ======== SCALE: 1024 jobs; job = 512 thr x 8 channels x 1 f4 ========
    #define PHASE_SCALE(B0)                                                   \
    {                                                                         \
        for (int j = bid; j < 1024; j += GRID) {                              \
            int idx = j * NT + tid;                                           \
            int g  = idx & 1023;                                              \
            int cs = (idx >> 10) & 31;                                        \
            int b  = (B0) + (idx >> 15);                                      \
            float4 s = __ldg(reinterpret_cast<const float4*>(g_scale)         \
                             + (size_t)b * HW4 + g);                          \
            const float4* xb = reinterpret_cast<const float4*>(x)             \
                + ((size_t)b * NC + cs * 8) * HW4 + g;                        \
            float4* ob = reinterpret_cast<float4*>(out)                       \
                + ((size_t)b * NC + cs * 8) * HW4 + g;                        \
            _Pragma("unroll")                                                 \
            for (int c = 0; c < 8; c++) {                                     \
                float4 v = __ldcs(xb + c * HW4);                              \
                v.x *= s.x; v.y *= s.y; v.z *= s.z; v.w *= s.w;               \
                __stcs(ob + c * HW4, v);                                      \
            }                                                                 \
        }                                                                     \
    }

    // ------------------------- pipeline -----------------------------------
    PHASE_REDUCE(0);        gbar(0);
    PHASE_CONV(0);          gbar(1);
    PHASE_SCALE(0);                         // c0 x-reads are L2-hot
    PHASE_REDUCE(CHUNK);    gbar(2);        // overlaps with late S(c0) CTAs
    PHASE_CONV(CHUNK);      gbar(3);
    PHASE_SCALE(CHUNK);
}

extern "C" void kernel_launch(void* const* d_in, const int* in_sizes, int n_in,
                              void* d_out, int out_size)
{
    const float* x = (const float*)d_in[0];
    const float* w = (const float*)d_in[1];
    float* out = (float*)d_out;

    persistent_kernel<<<GRID, NT>>>(x, w, out);
}

// round 12
// speedup vs baseline: 1.3413x; 1.3413x over previous
#include <cuda_runtime.h>
#include <math.h>

#define NB 32
#define NC 256
#define NH 64
#define NW 64
#define HW 4096
#define HW4 1024
#define KS 7
#define PAD 3
#define CPI 4               // CTAs per image
#define CPC 64              // channels per CTA
#define NT 1024
#define GRID (NB * CPI)     // 128 CTAs, all co-resident (<=148 SMs)

// partial stats [b][cpi][2][HW], combined s-plane, barrier state
__device__ float g_part[(size_t)NB * CPI * 2 * HW];
__device__ float g_splane[NB * HW];
__device__ unsigned g_cnt1[NB], g_cnt2[NB];
__device__ volatile unsigned g_flag1[NB], g_flag2[NB];

// image-local barrier: 4 CTAs arrive; replay-safe sense reversal
__device__ __forceinline__ void img_barrier(unsigned* cnt, volatile unsigned* flag)
{
    __threadfence();          // release: every thread's prior global stores
    __syncthreads();
    if (threadIdx.x == 0) {
        unsigned s = *flag;
        unsigned v = atomicAdd(cnt, 1u);
        if (v == CPI - 1) {
            *cnt = 0;
            __threadfence();
            *flag = s ^ 1u;
        } else {
            while (*flag == s) { __nanosleep(32); }
        }
        __threadfence();      // acquire
    }
    __syncthreads();
}

__global__ void __launch_bounds__(NT, 1) fused_kernel(const float* __restrict__ x,
                                                      const float* __restrict__ wgt,
                                                      float* __restrict__ out)
{
    __shared__ float2 st[HW];          // (max, mean) per pixel, 32 KB
    __shared__ float  sw[2 * KS * KS];

    const int tid = threadIdx.x;
    const int b   = blockIdx.x >> 2;
    const int cpi = blockIdx.x & 3;

    if (tid < 2 * KS * KS) sw[tid] = wgt[tid];

    const int g = tid;                 // this thread's float4 pixel-group (0..1023)
    const float4* xb = reinterpret_cast<const float4*>(x)
                     + ((size_t)b * NC + cpi * CPC) * HW4 + g;

    // ---------------- phase 1: reduce own 64 channels ----------------------
    float4 mx = make_float4(-INFINITY, -INFINITY, -INFINITY, -INFINITY);
    float4 sm = make_float4(0.f, 0.f, 0.f, 0.f);

    #pragma unroll 8
    for (int c = 0; c < CPC; c++) {
        float4 v = __ldg(xb + c * HW4);
        mx.x = fmaxf(mx.x, v.x);  sm.x += v.x;
        mx.y = fmaxf(mx.y, v.y);  sm.y += v.y;
        mx.z = fmaxf(mx.z, v.z);  sm.z += v.z;
        mx.w = fmaxf(mx.w, v.w);  sm.w += v.w;
    }

    {   // publish partial
        float4* pp = reinterpret_cast<float4*>(g_part) + (size_t)(b * CPI + cpi) * 2 * HW4;
        pp[g]       = mx;
        pp[HW4 + g] = sm;
    }

    img_barrier(&g_cnt1[b], &g_flag1[b]);

    // ---------------- phase 2a: combine 4 partials -> smem stats -----------
    #pragma unroll
    for (int q = 0; q < CPI; q++) {
        if (q == cpi) continue;
        const float4* qq = reinterpret_cast<const float4*>(g_part)
                         + (size_t)(b * CPI + q) * 2 * HW4;
        float4 m = __ldcg(qq + g);
        float4 s = __ldcg(qq + HW4 + g);
        mx.x = fmaxf(mx.x, m.x);  sm.x += s.x;
        mx.y = fmaxf(mx.y, m.y);  sm.y += s.y;
        mx.z = fmaxf(mx.z, m.z);  sm.z += s.z;
        mx.w = fmaxf(mx.w, m.w);  sm.w += s.w;
    }
    {
        const float inv = 1.0f / (float)NC;
        st[4 * g + 0] = make_float2(mx.x, sm.x * inv);
        st[4 * g + 1] = make_float2(mx.y, sm.y * inv);
        st[4 * g + 2] = make_float2(mx.z, sm.z * inv);
        st[4 * g + 3] = make_float2(mx.w, sm.w * inv);
    }
    __syncthreads();

    // ---------------- phase 2b: conv for this CTA's quarter ----------------
    // one pixel per thread; consecutive lanes = consecutive w -> conflict-free
    {
        int p = cpi * 1024 + tid;
        int h = p >> 6;
        int w = p & 63;
        float acc = 0.f;
        #pragma unroll
        for (int kh = 0; kh < KS; kh++) {
            int ih = h + kh - PAD;
            if (ih < 0 || ih >= NH) continue;
            #pragma unroll
            for (int kw = 0; kw < KS; kw++) {
                int iw = w + kw - PAD;
                if (iw < 0 || iw >= NW) continue;
                float2 v = st[ih * NW + iw];
                acc += v.x * sw[kh * KS + kw] + v.y * sw[KS * KS + kh * KS + kw];
            }
        }
        g_splane[b * HW + p] = 1.0f / (1.0f + __expf(-acc));
    }

    img_barrier(&g_cnt2[b], &g_flag2[b]);

    // ---------------- phase 3: out = x * s (x re-read is L2-hot) -----------
    {
        float4 s4 = __ldcg(reinterpret_cast<const float4*>(g_splane) + (size_t)b * HW4 + g);
        float4* ob = reinterpret_cast<float4*>(out)
                   + ((size_t)b * NC + cpi * CPC) * HW4 + g;

        // reverse channel order: freshest L2 lines first
        #pragma unroll 4
        for (int c = CPC - 1; c >= 0; c--) {
            float4 v = __ldcs(xb + c * HW4);   // last use: evict-first
            v.x *= s4.x; v.y *= s4.y; v.z *= s4.z; v.w *= s4.w;
            __stcs(ob + c * HW4, v);           // streaming store
        }
    }
}

extern "C" void kernel_launch(void* const* d_in, const int* in_sizes, int n_in,
                              void* d_out, int out_size)
{
    const float* x = (const float*)d_in[0];
    const float* w = (const float*)d_in[1];
    float* out = (float*)d_out;

    fused_kernel<<<GRID, NT>>>(x, w, out);
}

// round 15
// speedup vs baseline: 1.4448x; 1.0772x over previous
#include <cuda_runtime.h>
#include <math.h>

#define NB 32
#define NC 256
#define NH 64
#define NW 64
#define HW (NH*NW)          // 4096
#define HW4 (HW/4)          // 1024 float4 groups per (b,c) plane
#define KS 7
#define PAD 3

#define CHUNK 16            // images per chunk

// partial stats: [half][b][hw]  (half 0 = ch 0..127, half 1 = ch 128..255)
__device__ float g_pmax[2 * NB * HW];
__device__ float g_psum[2 * NB * HW];
__device__ float g_scale[NB * HW];       // sigmoid(conv)

// ---------------------------------------------------------------------------
// reduce job: one block = 32 float4-pixel-groups x 16 channel-splits x 1 half.
// rbid in [0, 1024) per chunk. 8 channels per thread.
// ---------------------------------------------------------------------------
__device__ __forceinline__ void reduce_block(const float* __restrict__ x,
                                             int b0, int rbid, int tid)
{
    __shared__ float4 s_max[16][32];
    __shared__ float4 s_sum[16][32];

    int pix = tid & 31;
    int cs  = tid >> 5;               // 0..15
    int pairid = rbid >> 1;
    int half   = rbid & 1;

    int gp = pairid * 32 + pix;       // chunk-local f4 group
    int b  = b0 + (gp >> 10);
    int g  = gp & 1023;

    const float4* xb = reinterpret_cast<const float4*>(x)
                     + ((size_t)b * NC + half * 128 + cs * 8) * HW4 + g;

    float4 mx = make_float4(-INFINITY, -INFINITY, -INFINITY, -INFINITY);
    float4 sm = make_float4(0.f, 0.f, 0.f, 0.f);

    #pragma unroll
    for (int c = 0; c < 8; c++) {
        float4 v = __ldg(xb + c * HW4);
        mx.x = fmaxf(mx.x, v.x);  sm.x += v.x;
        mx.y = fmaxf(mx.y, v.y);  sm.y += v.y;
        mx.z = fmaxf(mx.z, v.z);  sm.z += v.z;
        mx.w = fmaxf(mx.w, v.w);  sm.w += v.w;
    }

    s_max[cs][pix] = mx;
    s_sum[cs][pix] = sm;
    __syncthreads();

    if (cs == 0) {
        #pragma unroll
        for (int k = 1; k < 16; k++) {
            float4 m = s_max[k][pix];
            float4 s = s_sum[k][pix];
            mx.x = fmaxf(mx.x, m.x);  sm.x += s.x;
            mx.y = fmaxf(mx.y, m.y);  sm.y += s.y;
            mx.z = fmaxf(mx.z, m.z);  sm.z += s.z;
            mx.w = fmaxf(mx.w, m.w);  sm.w += s.w;
        }
        size_t o = ((size_t)half * NB + b) * HW4 + g;
        reinterpret_cast<float4*>(g_pmax)[o] = mx;
        reinterpret_cast<float4*>(g_psum)[o] = sm;
    }
}

// ---------------------------------------------------------------------------
// scale job: out = x * scale.  sbid in [0, 1024) per chunk, 512 threads.
// chunk-local idx bits: [b:4][cs:5][g:10], 8 channels per thread.
// ---------------------------------------------------------------------------
__device__ __forceinline__ void scale_block(const float* __restrict__ x,
                                            float* __restrict__ out,
                                            int b0, int sbid, int tid)
{
    int idx = sbid * 512 + tid;
    int g  = idx & 1023;
    int cs = (idx >> 10) & 31;
    int b  = b0 + (idx >> 15);

    float4 s = __ldg(reinterpret_cast<const float4*>(g_scale) + (size_t)b * HW4 + g);

    const float4* xb = reinterpret_cast<const float4*>(x)
                     + ((size_t)b * NC + cs * 8) * HW4 + g;
    float4* ob = reinterpret_cast<float4*>(out)
               + ((size_t)b * NC + cs * 8) * HW4 + g;

    #pragma unroll
    for (int c = 0; c < 8; c++) {
        float4 v = __ldcs(xb + c * HW4);   // last use of x: evict-first
        v.x *= s.x; v.y *= s.y; v.z *= s.z; v.w *= s.w;
        __stcs(ob + c * HW4, v);           // streaming store
    }
}

__global__ void __launch_bounds__(512) reduce_kernel(const float* __restrict__ x, int b0)
{
    reduce_block(x, b0, blockIdx.x, threadIdx.x);
}

__global__ void __launch_bounds__(512) scale_kernel(const float* __restrict__ x,
                                                    float* __restrict__ out, int b0)
{
    scale_block(x, out, b0, blockIdx.x, threadIdx.x);
}

// Fused: even blocks run reduce(next chunk) — dispatched first so its DRAM
// reads start immediately — odd blocks run scale(current chunk).
__global__ void __launch_bounds__(512) fused_kernel(const float* __restrict__ x,
                                                    float* __restrict__ out,
                                                    int b0s, int b0r)
{
    if (blockIdx.x & 1) scale_block(x, out, b0s, blockIdx.x >> 1, threadIdx.x);
    else                reduce_block(x, b0r, blockIdx.x >> 1, threadIdx.x);
}

// ---------------------------------------------------------------------------
// conv: 1 thread = 1 pixel. Block = 128 threads = one 2-row strip of one
// image. Grid per chunk = 16 img x 32 strips = 512 blocks. Combines the two
// channel-halves into a padded smem tile (2 planes x 8 rows x 72 cols), then
// 7x7 conv + sigmoid -> g_scale. All stats reads are L2-resident.
// ---------------------------------------------------------------------------
#define CTW 72
__global__ void __launch_bounds__(128) conv_kernel(const float* __restrict__ wgt, int b0)
{
    __shared__ float sw[2 * KS * KS];
    __shared__ float st[2][8][CTW];

    int tid = threadIdx.x;
    if (tid < 2 * KS * KS) sw[tid] = wgt[tid];

    int b  = b0 + (blockIdx.x >> 5);
    int h0 = (blockIdx.x & 31) * 2;     // strip start row

    const float* pmax0 = g_pmax + (size_t)b * HW;
    const float* pmax1 = g_pmax + (size_t)(NB + b) * HW;
    const float* psum0 = g_psum + (size_t)b * HW;
    const float* psum1 = g_psum + (size_t)(NB + b) * HW;

    // fill 2 planes x 8 rows x 72 cols (rows h0-3 .. h0+4, cols -3 .. 68)
    #pragma unroll
    for (int i = tid; i < 2 * 8 * CTW; i += 128) {
        int plane = i / (8 * CTW);
        int rem   = i % (8 * CTW);
        int r = rem / CTW;
        int c = rem % CTW;
        int gr = h0 - PAD + r;
        int gc = c - PAD;
        float v = 0.f;
        if (gr >= 0 && gr < NH && gc >= 0 && gc < NW) {
            int off = gr * NW + gc;
            v = (plane == 0) ? fmaxf(__ldg(pmax0 + off), __ldg(pmax1 + off))
                             : (__ldg(psum0 + off) + __ldg(psum1 + off)) * (1.0f / (float)NC);
        }
        st[plane][r][c] = v;
    }
    __syncthreads();

    int h_l = tid >> 6;               // 0..1
    int w   = tid & 63;               // 0..63

    float acc = 0.f;
    #pragma unroll
    for (int kh = 0; kh < KS; kh++) {
        #pragma unroll
        for (int kw = 0; kw < KS; kw++) {
            int r = h_l + kh;
            int c = w + kw;
            acc += st[0][r][c] * sw[kh * KS + kw]
                 + st[1][r][c] * sw[KS * KS + kh * KS + kw];
        }
    }

    g_scale[(size_t)b * HW + (h0 + h_l) * NW + w] = 1.0f / (1.0f + __expf(-acc));
}

extern "C" void kernel_launch(void* const* d_in, const int* in_sizes, int n_in,
                              void* d_out, int out_size)
{
    const float* x = (const float*)d_in[0];
    const float* w = (const float*)d_in[1];
    float* out = (float*)d_out;

    // chunk 0: images 0..15, chunk 1: images 16..31
    reduce_kernel<<<1024, 512>>>(x, 0);
    conv_kernel<<<512, 128>>>(w, 0);
    fused_kernel<<<2048, 512>>>(x, out, 0, CHUNK);   // reduce(c1) || scale(c0)
    conv_kernel<<<512, 128>>>(w, CHUNK);
    scale_kernel<<<1024, 512>>>(x, out, CHUNK);
}